// round 8
// baseline (speedup 1.0000x reference)
#include <cuda_runtime.h>
#include <cstdint>

#define NN   32
#define CC   64
#define HH   112
#define WW   112
#define HW   (HH*WW)        // 12544
#define OO   64
#define TAPS 9
#define WSTRIDE 10          // padded weight row (16B-aligned rows: 80 bytes)
#define OB   32             // output channels per block (o-split)

typedef unsigned long long u64;

// Static device scratch (no allocation)
__device__ __align__(16) u64 g_packed[NN * HW];        // bit c = (A[n][c][y][x] > 0)
__device__ __align__(16) u64 g_wbits[OO * WSTRIDE];    // padded rows of 10
__device__ float             g_fixf[16 * OO];          // per edge-class per o correction (float)

// Full adder (carry-save) in pure 3-input form:
// s = XOR3 -> one LOP3(0x96) per 32-bit half; c = MAJ3 -> one LOP3(0xE8) per half.
__device__ __forceinline__ void csa(u64& s, u64& c, u64 x, u64 y, u64 z) {
    s = x ^ y ^ z;
    c = (x & y) | (x & z) | (y & z);
}

// ---------------------------------------------------------------------------
// Kernel 1: pack weights. One warp per (o,t); lane covers channels lane, lane+32.
// ---------------------------------------------------------------------------
__global__ void pack_weights_kernel(const float* __restrict__ w) {
    int wid  = blockIdx.x * (blockDim.x >> 5) + (threadIdx.x >> 5);
    int lane = threadIdx.x & 31;
    if (wid >= OO * TAPS) return;
    int o = wid / TAPS, t = wid % TAPS;
    float v0 = w[(o * CC + lane) * TAPS + t];
    float v1 = w[(o * CC + lane + 32) * TAPS + t];
    unsigned b0 = __ballot_sync(0xFFFFFFFFu, v0 > 0.0f);
    unsigned b1 = __ballot_sync(0xFFFFFFFFu, v1 > 0.0f);
    if (lane == 0)
        g_wbits[o * WSTRIDE + t] = (u64)b0 | ((u64)b1 << 32);
}

// ---------------------------------------------------------------------------
// Kernel 1b: border fix table (float). blockIdx.x = edge class mask m
// (bit0: y==0, bit1: y==111, bit2: x==0, bit3: x==111), threadIdx.x = o.
// fix = 2*sum_{invalid taps} popc(w) - 64*n_missing ;  class 0 -> 0.0f
// ---------------------------------------------------------------------------
__global__ void pack_fix_kernel() {
    int m = blockIdx.x;     // 0..15
    int o = threadIdx.x;    // 0..63
    bool T = m & 1, B = m & 2, L = m & 4, R = m & 8;
    int corr = 0, nmiss = 0;
#pragma unroll
    for (int t = 0; t < 9; t++) {
        int r = t / 3, c = t % 3;
        bool inv = (T && r == 0) || (B && r == 2) || (L && c == 0) || (R && c == 2);
        if (inv) {
            corr += __popcll(g_wbits[o * WSTRIDE + t]);
            nmiss++;
        }
    }
    g_fixf[m * OO + o] = (float)(2 * corr - CC * nmiss);
}

// ---------------------------------------------------------------------------
// Kernel 2: pack activations. Each thread packs 4 consecutive pixels via
// float4 loads per channel.
// ---------------------------------------------------------------------------
__global__ void pack_act_kernel(const float* __restrict__ act) {
    int tidg = blockIdx.x * blockDim.x + threadIdx.x;
    int p0   = tidg * 4;
    int n    = p0 / HW;
    int p    = p0 - n * HW;

    const float* base = act + (long)(n * CC) * HW + p;
    u64 w0 = 0, w1 = 0, w2 = 0, w3 = 0;
#pragma unroll
    for (int c = 0; c < CC; c++) {
        float4 v = *(const float4*)(base + (long)c * HW);
        w0 |= (u64)(v.x > 0.0f) << c;
        w1 |= (u64)(v.y > 0.0f) << c;
        w2 |= (u64)(v.z > 0.0f) << c;
        w3 |= (u64)(v.w > 0.0f) << c;
    }
    ulonglong2* dst = (ulonglong2*)(g_packed + p0);
    dst[0] = make_ulonglong2(w0, w1);
    dst[1] = make_ulonglong2(w2, w3);
}

// ---------------------------------------------------------------------------
// Kernel 3: binary conv, 4-CSA compressed popcount (XOR3/MAJ3), fused border.
// Thread: 4 pixels, window 3x6 words. Block (28,4)=112; grid (28,32,2).
// Per (o,px): 9 XOR + 4 CSA -> popc(s0)+popc(s1)+popc(s2)+2popc(s3)+4popc(c3).
// res = 576 - 2*acc via magic fma. Border classes corrected from smem table.
// ---------------------------------------------------------------------------
__global__ __launch_bounds__(112)
void bconv_kernel(float* __restrict__ out) {
    __shared__ __align__(16) u64 ws[OB * WSTRIDE];
    __shared__ float fix_s[16 * OB];

    int obase = blockIdx.z * OB;
    int t = threadIdx.y * 28 + threadIdx.x;
    for (int i = t; i < OB * WSTRIDE; i += 112)
        ws[i] = g_wbits[obase * WSTRIDE + i];
    for (int i = t; i < 16 * OB; i += 112)
        fix_s[i] = g_fixf[(i / OB) * OO + obase + (i % OB)];
    __syncthreads();

    int x0 = threadIdx.x * 4;
    int y  = blockIdx.x * 4 + threadIdx.y;
    int n  = blockIdx.y;

    const u64* pb = g_packed + (long)n * HW;

    // 3x6 window, zero for OOB (corrected via fix table)
    u64 a[3][6];
#pragma unroll
    for (int r = 0; r < 3; r++) {
        int yy = y - 1 + r;
        bool rv = (unsigned)yy < (unsigned)HH;
        const u64* row = pb + yy * WW;
#pragma unroll
        for (int c = 0; c < 6; c++) {
            int xx = x0 - 1 + c;
            bool v = rv && ((unsigned)xx < (unsigned)WW);
            a[r][c] = v ? row[xx] : 0ull;
        }
    }

    // Border class masks (per output pixel)
    int m_y = (y == 0 ? 1 : 0) | (y == 111 ? 2 : 0);
    int m0  = m_y | (x0 == 0 ? 4 : 0);
    int m3  = m_y | (x0 == 108 ? 8 : 0);
    bool anyb = (m0 | m3) != 0;

    const float MAGIC_SUB = 16777792.0f;  // 2^24 + 576

    float* ob = out + ((long)(n * OO + obase)) * HW + y * WW + x0;

#pragma unroll 2
    for (int o = 0; o < OB; o++) {
        const ulonglong2* wr2 = (const ulonglong2*)(ws + o * WSTRIDE);
        ulonglong2 wp0 = wr2[0], wp1 = wr2[1], wp2 = wr2[2], wp3 = wr2[3];
        u64 wv[9] = { wp0.x, wp0.y, wp1.x, wp1.y, wp2.x, wp2.y, wp3.x, wp3.y,
                      ws[o * WSTRIDE + 8] };

        float4 res;
#pragma unroll
        for (int px = 0; px < 4; px++) {
            u64 s0, s1, s2, s3, c0, c1, c2, c3;
            csa(s0, c0, a[0][px] ^ wv[0], a[0][px + 1] ^ wv[1], a[0][px + 2] ^ wv[2]);
            csa(s1, c1, a[1][px] ^ wv[3], a[1][px + 1] ^ wv[4], a[1][px + 2] ^ wv[5]);
            csa(s2, c2, a[2][px] ^ wv[6], a[2][px + 1] ^ wv[7], a[2][px + 2] ^ wv[8]);
            csa(s3, c3, c0, c1, c2);

            int acc = __popcll(s0) + __popcll(s1) + __popcll(s2)
                    + 2 * __popcll(s3) + 4 * __popcll(c3);
            float v = fmaf(-2.0f, __int_as_float(0x4B000000 | acc), MAGIC_SUB);
            if (px == 0) res.x = v;
            else if (px == 1) res.y = v;
            else if (px == 2) res.z = v;
            else res.w = v;
        }

        if (anyb) {   // warp-uniform false for all interior warps
            res.x += fix_s[m0  * OB + o];
            res.y += fix_s[m_y * OB + o];
            res.z += fix_s[m_y * OB + o];
            res.w += fix_s[m3  * OB + o];
        }

        *(float4*)(ob + (long)o * HW) = res;
    }
}

// ---------------------------------------------------------------------------
extern "C" void kernel_launch(void* const* d_in, const int* in_sizes, int n_in,
                              void* d_out, int out_size) {
    const float* act = (const float*)d_in[0];   // [32,64,112,112]
    const float* w   = (const float*)d_in[1];   // [64*64*9, 1]
    float* out       = (float*)d_out;           // [32,64,112,112]

    pack_weights_kernel<<<72, 256>>>(w);
    pack_fix_kernel<<<16, OO>>>();

    pack_act_kernel<<<(NN * HW / 4) / 128, 128>>>(act);

    dim3 block(28, 4);
    dim3 grid(HH / 4, NN, 2);
    bconv_kernel<<<grid, block>>>(out);
}